// round 8
// baseline (speedup 1.0000x reference)
#include <cuda_runtime.h>
#include <cuda_fp16.h>
#include <cstdint>

#define H_ 3
#define L_ 2
#define B_ 16
#define S_ 512
#define D_ 512
#define F_ (H_ * L_ * D_)   // 3072

// Scratch (no cudaMalloc allowed) — fp16 operand buffers
__device__ __align__(16) __half g_adjH[(size_t)H_ * B_ * S_ * S_];  // 25 MB
__device__ __align__(16) __half g_AxH[(size_t)H_ * B_ * S_ * D_];   // 25 MB
__device__ __align__(16) __half g_finH[(size_t)B_ * S_ * F_];       // 50 MB
__device__ __align__(16) __half g_XTH[(size_t)H_ * B_ * D_ * S_];   // 25 MB
__device__ __align__(16) __half g_X0TH[(size_t)B_ * D_ * S_];       // 8 MB
__device__ __align__(16) __half g_WgH[(size_t)H_ * L_ * D_ * D_];   // 3 MB
__device__ __align__(16) __half g_WoH[(size_t)D_ * F_];             // 3 MB
__device__ float g_denom[H_ * B_ * S_];                             // 96 KB

// ---------------------------------------------------------------------------
__device__ __forceinline__ uint32_t smem_u32(const void* p) {
    uint32_t a;
    asm("{ .reg .u64 t; cvta.to.shared.u64 t, %1; cvt.u32.u64 %0, t; }" : "=r"(a) : "l"(p));
    return a;
}
#define CP_ASYNC16(dst, src) \
    asm volatile("cp.async.cg.shared.global [%0], [%1], 16;" :: "r"(dst), "l"(src))
#define CP_COMMIT() asm volatile("cp.async.commit_group;")
#define CP_WAIT(n)  asm volatile("cp.async.wait_group %0;" :: "n"(n))

#define LDSM4(r0, r1, r2, r3, addr) \
    asm volatile("ldmatrix.sync.aligned.m8n8.x4.shared.b16 {%0,%1,%2,%3}, [%4];" \
        : "=r"(r0), "=r"(r1), "=r"(r2), "=r"(r3) : "r"(addr))

#define MMA_F16(c, a, b0, b1) \
    asm volatile("mma.sync.aligned.m16n8k16.row.col.f32.f16.f16.f32 " \
        "{%0,%1,%2,%3}, {%4,%5,%6,%7}, {%8,%9}, {%0,%1,%2,%3};" \
        : "+f"((c)[0]), "+f"((c)[1]), "+f"((c)[2]), "+f"((c)[3]) \
        : "r"((a)[0]), "r"((a)[1]), "r"((a)[2]), "r"((a)[3]), \
          "r"(b0), "r"(b1))

__device__ __forceinline__ __half toh(float x)  { return __float2half_rn(x); }
__device__ __forceinline__ __half toh(__half x) { return x; }

// ---------------------------------------------------------------------------
// Per row (h,b,s): den = 1 + sum_t adj (exact fp32), adjH = half(adj)
// ---------------------------------------------------------------------------
__global__ void denom_round_kernel(const float* __restrict__ adj,
                                   float* __restrict__ den,
                                   __half* __restrict__ adjH)
{
    int gw = (blockIdx.x * blockDim.x + threadIdx.x) >> 5;
    int lane = threadIdx.x & 31;
    if (gw >= H_ * B_ * S_) return;
    const float4* p = (const float4*)(adj + (long)gw * S_);
    __half2* q = (__half2*)(adjH + (long)gw * S_);
    float s = 0.f;
    #pragma unroll 2
    for (int i = lane; i < S_ / 4; i += 32) {
        float4 v = p[i];
        s += v.x + v.y + v.z + v.w;
        q[2 * i]     = __floats2half2_rn(v.x, v.y);
        q[2 * i + 1] = __floats2half2_rn(v.z, v.w);
    }
    #pragma unroll
    for (int o = 16; o > 0; o >>= 1) s += __shfl_xor_sync(0xffffffffu, s, o);
    if (lane == 0) den[gw] = s + 1.0f;
}

__global__ void roundcopy_half(const float* __restrict__ src,
                               __half* __restrict__ dst, int n4)
{
    int i = blockIdx.x * blockDim.x + threadIdx.x;
    if (i >= n4) return;
    float4 v = ((const float4*)src)[i];
    ((__half2*)dst)[2 * i]     = __floats2half2_rn(v.x, v.y);
    ((__half2*)dst)[2 * i + 1] = __floats2half2_rn(v.z, v.w);
}

// ---------------------------------------------------------------------------
// XT[h][b][d][s] = half( X[...][s][d] )
// ---------------------------------------------------------------------------
template <typename T>
__global__ void transpose_kernel(const T* __restrict__ X, int ldx,
                                 long xHead, long xBatch,
                                 __half* __restrict__ XT, long tHead)
{
    __shared__ __half t[32][33];
    int z = blockIdx.z;
    int hz = z >> 4, bz = z & 15;
    int s0 = blockIdx.x * 32, d0 = blockIdx.y * 32;
    const T* Xb = X + (long)hz * xHead + (long)bz * xBatch;
    __half* Tb = XT + (long)hz * tHead + (long)bz * D_ * S_;
    int tx = threadIdx.x, ty = threadIdx.y;  // 32 x 8
    #pragma unroll
    for (int i = 0; i < 32; i += 8)
        t[ty + i][tx] = toh(Xb[(long)(s0 + ty + i) * ldx + d0 + tx]);
    __syncthreads();
    #pragma unroll
    for (int i = 0; i < 32; i += 8)
        Tb[(long)(d0 + ty + i) * S_ + s0 + tx] = t[tx][ty + i];
}

// ---------------------------------------------------------------------------
// FP16 mma.sync GEMM (fp32 accum): C[M,N] = A[M,K] * B[N,K]^T, K-major halves.
// CTA 128x256, 8 warps of 64x64, BK=32, 4-stage cp.async, 1 CTA/SM.
// z encodes (head = z>>4, batch = z&15).
// MODE 0: Chalf = acc + epi[m][n]             (epi fp32 or fp16 per EPI_HALF)
// MODE 1: Chalf = relu((acc + biasScale*bias[n]) / denom[z,m])
// MODE 2: Cfloat = acc + bias[n] + epi[m][n]  (epi fp32)
// ---------------------------------------------------------------------------
constexpr int BM = 128, BN = 256, BK = 32;        // BK in halves (64 bytes)
constexpr int ROWH = 40;                          // padded row halves (80 B)
constexpr int A_STG_BYTES = BM * ROWH * 2;        // 10240
constexpr int B_STG_BYTES = BN * ROWH * 2;        // 20480
constexpr int STAGE_BYTES = A_STG_BYTES + B_STG_BYTES;  // 30720
constexpr int NSTAGE = 4;
constexpr int SMEM_SZ = NSTAGE * STAGE_BYTES;     // 122880

template <int MODE, bool EPI_HALF>
__global__ __launch_bounds__(256, 1)
void mma_gemm(const __half* __restrict__ A, const __half* __restrict__ Bm,
              void* __restrict__ C,
              int K, int lda, int ldb, int ldc,
              long aHead, long aBatch, long bHead, long bBatch,
              long cHead, long cBatch,
              const void* __restrict__ epi, int epiLd, long epiHead, long epiBatch,
              const float* __restrict__ bias, long biasHead, float biasScale,
              const float* __restrict__ denom, int denomStride)
{
    extern __shared__ char smemc[];
    const int tid = threadIdx.x;
    const int wid = tid >> 5, lane = tid & 31;
    const int bx = blockIdx.x, by = blockIdx.y, z = blockIdx.z;
    const int hz = z >> 4, bz = z & 15;

    const uint32_t sbase = smem_u32(smemc);

    const __half* Ab = A + (long)hz * aHead + (long)bz * aBatch + (long)(by * BM) * lda;
    const __half* Bb = Bm + (long)hz * bHead + (long)bz * bBatch + (long)(bx * BN) * ldb;

    // cp.async mapping:
    //  A: 2 threads per 64B row (2 x 16B chunks each)
    //  B: 1 thread per 64B row (4 x 16B chunks)
    const int arow = tid >> 1;
    const int ach  = (tid & 1) * 16;    // half offset in row

    auto load_stage = [&](int s, int kt) {
        const long k0 = (long)kt * BK;
        {
            const __half* g = Ab + (long)arow * lda + k0 + ach;
            uint32_t d = sbase + (uint32_t)(s * STAGE_BYTES)
                       + (uint32_t)(arow * ROWH + ach) * 2u;
            CP_ASYNC16(d, g);
            CP_ASYNC16(d + 16u, g + 8);
        }
        {
            const __half* g = Bb + (long)tid * ldb + k0;
            uint32_t d = sbase + (uint32_t)(s * STAGE_BYTES) + (uint32_t)A_STG_BYTES
                       + (uint32_t)(tid * ROWH) * 2u;
            #pragma unroll
            for (int i = 0; i < 4; ++i)
                CP_ASYNC16(d + i * 16u, g + i * 8);
        }
    };

    // warp tiling: 2 (m) x 4 (n); each warp 64x64
    const int m0 = (wid & 1) * 64;
    const int n0 = (wid >> 1) * 64;
    const int lq = lane >> 2;
    const int lr = lane & 3;

    // ldmatrix base addresses (stage 0, ks = 0); row stride 80 B (20 banks,
    // gcd(20,32)=4 -> 8 distinct row banks; 16B/row -> conflict-free LDSM)
    const uint32_t aAddr0 = sbase
        + (uint32_t)((m0 + ((lane >> 3) & 1) * 8 + (lane & 7)) * ROWH) * 2u
        + (uint32_t)(lane >> 4) * 16u;
    const uint32_t bAddr0 = sbase + (uint32_t)A_STG_BYTES
        + (uint32_t)((n0 + (lane >> 4) * 8 + (lane & 7)) * ROWH) * 2u
        + (uint32_t)((lane >> 3) & 1) * 16u;

    float c[4][8][4];
    #pragma unroll
    for (int mi = 0; mi < 4; ++mi)
        #pragma unroll
        for (int ni = 0; ni < 8; ++ni)
            #pragma unroll
            for (int j = 0; j < 4; ++j) c[mi][ni][j] = 0.f;

    const int numK = K >> 5;   // BK=32; >= 16 for all our GEMMs

    load_stage(0, 0); CP_COMMIT();
    load_stage(1, 1); CP_COMMIT();
    load_stage(2, 2); CP_COMMIT();

    for (int kt = 0; kt < numK; ++kt) {
        const int rem = numK - 1 - kt;
        if (rem >= 2)      { CP_WAIT(2); }
        else if (rem == 1) { CP_WAIT(1); }
        else               { CP_WAIT(0); }
        __syncthreads();   // all warps done reading stage (kt-1)%4 before refill
        if (kt + 3 < numK) {
            load_stage((kt + 3) & 3, kt + 3);
            CP_COMMIT();
        }

        const uint32_t sOff = (uint32_t)(kt & 3) * STAGE_BYTES;
        #pragma unroll
        for (int ks = 0; ks < 2; ++ks) {          // two k16 steps in BK=32
            const uint32_t kOff = sOff + (uint32_t)ks * 32u;   // 16 halves
            uint32_t a[4][4], b[4][4];
            #pragma unroll
            for (int p = 0; p < 4; ++p)
                LDSM4(b[p][0], b[p][1], b[p][2], b[p][3],
                      bAddr0 + kOff + (uint32_t)p * (16u * ROWH * 2u));
            #pragma unroll
            for (int mi = 0; mi < 4; ++mi)
                LDSM4(a[mi][0], a[mi][1], a[mi][2], a[mi][3],
                      aAddr0 + kOff + (uint32_t)mi * (16u * ROWH * 2u));
            #pragma unroll
            for (int mi = 0; mi < 4; ++mi)
                #pragma unroll
                for (int ni = 0; ni < 8; ++ni)
                    MMA_F16(c[mi][ni], a[mi], b[ni >> 1][(ni & 1) * 2],
                            b[ni >> 1][(ni & 1) * 2 + 1]);
        }
    }

    // ---------------- epilogue ----------------
    const float* biasP = (MODE == 1 || MODE == 2) ? (bias + (long)hz * biasHead) : nullptr;

    #pragma unroll
    for (int mi = 0; mi < 4; ++mi) {
        const int r0 = by * BM + m0 + mi * 16 + lq;
        float invd0 = 1.f, invd1 = 1.f;
        if (MODE == 1) {
            invd0 = 1.0f / denom[(long)z * denomStride + r0];
            invd1 = 1.0f / denom[(long)z * denomStride + r0 + 8];
        }
        #pragma unroll
        for (int ni = 0; ni < 8; ++ni) {
            const int col = bx * BN + n0 + ni * 8 + 2 * lr;
            float v00 = c[mi][ni][0], v01 = c[mi][ni][1];
            float v10 = c[mi][ni][2], v11 = c[mi][ni][3];
            if (MODE == 0) {
                if (EPI_HALF) {
                    const __half* Eb = (const __half*)epi
                        + (long)hz * epiHead + (long)bz * epiBatch;
                    float2 e0 = __half22float2(*(const __half2*)(Eb + (long)r0 * epiLd + col));
                    float2 e1 = __half22float2(*(const __half2*)(Eb + (long)(r0 + 8) * epiLd + col));
                    v00 += e0.x; v01 += e0.y; v10 += e1.x; v11 += e1.y;
                } else {
                    const float* Eb = (const float*)epi
                        + (long)hz * epiHead + (long)bz * epiBatch;
                    float2 e0 = *(const float2*)(Eb + (long)r0 * epiLd + col);
                    float2 e1 = *(const float2*)(Eb + (long)(r0 + 8) * epiLd + col);
                    v00 += e0.x; v01 += e0.y; v10 += e1.x; v11 += e1.y;
                }
                __half* Cb = (__half*)C + (long)hz * cHead + (long)bz * cBatch;
                *(__half2*)(Cb + (long)r0 * ldc + col)       = __floats2half2_rn(v00, v01);
                *(__half2*)(Cb + (long)(r0 + 8) * ldc + col) = __floats2half2_rn(v10, v11);
            } else if (MODE == 1) {
                const float b0 = biasScale * biasP[col];
                const float b1 = biasScale * biasP[col + 1];
                v00 = fmaxf((v00 + b0) * invd0, 0.f);
                v01 = fmaxf((v01 + b1) * invd0, 0.f);
                v10 = fmaxf((v10 + b0) * invd1, 0.f);
                v11 = fmaxf((v11 + b1) * invd1, 0.f);
                __half* Cb = (__half*)C + (long)hz * cHead + (long)bz * cBatch;
                *(__half2*)(Cb + (long)r0 * ldc + col)       = __floats2half2_rn(v00, v01);
                *(__half2*)(Cb + (long)(r0 + 8) * ldc + col) = __floats2half2_rn(v10, v11);
            } else {  // MODE 2: fp32 output, fp32 epi (residual) + bias
                const float* Eb = (const float*)epi;
                float2 e0 = *(const float2*)(Eb + (long)r0 * epiLd + col);
                float2 e1 = *(const float2*)(Eb + (long)(r0 + 8) * epiLd + col);
                const float b0 = biasP[col], b1 = biasP[col + 1];
                v00 += e0.x + b0; v01 += e0.y + b1;
                v10 += e1.x + b0; v11 += e1.y + b1;
                float* Cb = (float*)C;
                float2 w0 = {v00, v01}, w1 = {v10, v11};
                *(float2*)(Cb + (long)r0 * ldc + col) = w0;
                *(float2*)(Cb + (long)(r0 + 8) * ldc + col) = w1;
            }
        }
    }
}

// ---------------------------------------------------------------------------
extern "C" void kernel_launch(void* const* d_in, const int* in_sizes, int n_in,
                              void* d_out, int out_size)
{
    const float* adj = (const float*)d_in[0];   // [H,B,S,S]
    const float* x0  = (const float*)d_in[1];   // [B,S,D]
    const float* Wg  = (const float*)d_in[4];   // [H*L, D, D]
    const float* bg  = (const float*)d_in[5];   // [H*L, D]
    const float* Wo  = (const float*)d_in[6];   // [D, F]
    const float* bo  = (const float*)d_in[7];   // [D]
    float* out = (float*)d_out;                 // [B,S,D]

    __half *adjH, *AxH, *finH, *XTH, *X0TH, *WgH, *WoH;
    float* den;
    cudaGetSymbolAddress((void**)&adjH, g_adjH);
    cudaGetSymbolAddress((void**)&AxH,  g_AxH);
    cudaGetSymbolAddress((void**)&finH, g_finH);
    cudaGetSymbolAddress((void**)&XTH,  g_XTH);
    cudaGetSymbolAddress((void**)&X0TH, g_X0TH);
    cudaGetSymbolAddress((void**)&WgH,  g_WgH);
    cudaGetSymbolAddress((void**)&WoH,  g_WoH);
    cudaGetSymbolAddress((void**)&den,  g_denom);

    cudaFuncSetAttribute(mma_gemm<0, false>, cudaFuncAttributeMaxDynamicSharedMemorySize, SMEM_SZ);
    cudaFuncSetAttribute(mma_gemm<0, true>,  cudaFuncAttributeMaxDynamicSharedMemorySize, SMEM_SZ);
    cudaFuncSetAttribute(mma_gemm<1, false>, cudaFuncAttributeMaxDynamicSharedMemorySize, SMEM_SZ);
    cudaFuncSetAttribute(mma_gemm<2, false>, cudaFuncAttributeMaxDynamicSharedMemorySize, SMEM_SZ);

    // ---- prep: denom + fp16 operand copies ----
    denom_round_kernel<<<(H_ * B_ * S_) / 8, 256>>>(adj, den, adjH);
    roundcopy_half<<<(H_ * L_ * D_ * D_ / 4 + 255) / 256, 256>>>(Wg, WgH, H_ * L_ * D_ * D_ / 4);
    roundcopy_half<<<(D_ * F_ / 4 + 255) / 256, 256>>>(Wo, WoH, D_ * F_ / 4);
    transpose_kernel<float><<<dim3(16, 16, B_), dim3(32, 8)>>>(
        x0, D_, 0, (long)S_ * D_, X0TH, 0);

    const long SS = (long)S_ * S_, SD = (long)S_ * D_, SF = (long)S_ * F_;
    const long DS = (long)D_ * S_, DD = (long)D_ * D_;

    for (int l = 0; l < L_; ++l) {
        // GEMM1 (all heads): AxH[h] = adj[h] @ X + X
        if (l == 0) {
            mma_gemm<0, false><<<dim3(2, 4, H_ * B_), 256, SMEM_SZ>>>(
                adjH, X0TH, AxH,
                S_, S_, S_, D_,
                (long)B_ * SS, SS, 0, DS, (long)B_ * SD, SD,
                x0, D_, 0, SD,
                nullptr, 0, 0.f,
                nullptr, 0);
        } else {
            mma_gemm<0, true><<<dim3(2, 4, H_ * B_), 256, SMEM_SZ>>>(
                adjH, XTH, AxH,
                S_, S_, S_, D_,
                (long)B_ * SS, SS, (long)B_ * DS, DS, (long)B_ * SD, SD,
                finH, F_, (long)L_ * D_, SF,   // epi = prev layer output (fp16)
                nullptr, 0, 0.f,
                nullptr, 0);
        }

        // GEMM2 (all heads): finH[.., (h*L+l)*D ..] = relu((AxH @ Wg^T + 2b)/den)
        mma_gemm<1, false><<<dim3(2, 4, H_ * B_), 256, SMEM_SZ>>>(
            AxH, WgH + (long)l * DD, finH + (long)l * D_,
            D_, D_, D_, F_,
            (long)B_ * SD, SD, (long)L_ * DD, 0, (long)L_ * D_, SF,
            nullptr, 0, 0, 0,
            bg + (long)l * D_, (long)L_ * D_, 2.0f,
            den, S_);

        // layer-0 outputs -> transposed fp16 for layer-1 GEMM1 B operand
        if (l == 0)
            transpose_kernel<__half><<<dim3(16, 16, H_ * B_), dim3(32, 8)>>>(
                finH, F_, (long)L_ * D_, SF, XTH, (long)B_ * DS);
    }

    // Final: out = finH @ Wo^T + bo + x0   (M = B*S = 8192, K = F, fp32 out)
    mma_gemm<2, false><<<dim3(2, 64, 1), 256, SMEM_SZ>>>(
        finH, WoH, out,
        F_, F_, F_, D_,
        0, 0, 0, 0, 0, 0,
        x0, D_, 0, 0,
        bo, 0, 1.0f,
        nullptr, 0);
}